// round 1
// baseline (speedup 1.0000x reference)
#include <cuda_runtime.h>
#include <cstdint>
#include <cstddef>

#define NND 50000
#define NE  800000
#define HID 128

// ---------------- scratch (static device globals; no allocation) ----------------
__device__ float g_agg[(size_t)NND * 256];   // layer1 uses stride 128, layer2 stride 256
__device__ int   g_deg[NND];
__device__ float g_hn1[(size_t)NND * HID];
__device__ float g_A[(size_t)NND * HID];
__device__ float g_B[(size_t)NND * HID];

// ---------------- utility kernels ----------------
__global__ void k_zero_agg(size_t n) {
    size_t i = (size_t)blockIdx.x * blockDim.x + threadIdx.x;
    size_t stride = (size_t)gridDim.x * blockDim.x;
    for (; i < n; i += stride) g_agg[i] = 0.0f;
}

__global__ void k_zero_deg() {
    int i = blockIdx.x * blockDim.x + threadIdx.x;
    if (i < NND) g_deg[i] = 0;
}

__global__ void k_deg(const int* __restrict__ v) {
    int i = blockIdx.x * blockDim.x + threadIdx.x;
    if (i < NE) atomicAdd(&g_deg[v[i]], 1);
}

// ---------------- layer-1 scatter: agg1[v] += [nfeats[u] (64) | efeats[e] (64)] ----------------
__global__ void k_scatter1(const float* __restrict__ nf, const float* __restrict__ ef,
                           const int* __restrict__ u, const int* __restrict__ v) {
    int tid = blockIdx.x * blockDim.x + threadIdx.x;
    int e = tid >> 5;
    if (e >= NE) return;
    int q = tid & 31;                       // 32 lanes/edge, 4 floats/lane
    int uu = u[e], vv = v[e];
    float4 val;
    if (q < 16) val = *(const float4*)(nf + (size_t)uu * 64 + q * 4);
    else        val = *(const float4*)(ef + (size_t)e  * 64 + (q - 16) * 4);
    float* dst = g_agg + (size_t)vv * 128 + q * 4;
    atomicAdd(dst + 0, val.x);
    atomicAdd(dst + 1, val.y);
    atomicAdd(dst + 2, val.z);
    atomicAdd(dst + 3, val.w);
}

// ---------------- fused: he1 = relu(A1[u]+B1[v]+b); agg2[v] += [hn1[u] | he1] ----------------
__global__ void k_edge1(const int* __restrict__ u, const int* __restrict__ v,
                        const float* __restrict__ bias) {
    int tid = blockIdx.x * blockDim.x + threadIdx.x;
    int e = tid >> 5;
    if (e >= NE) return;
    int q = tid & 31;
    int f = q * 4;
    int uu = u[e], vv = v[e];
    float4 a  = *(const float4*)(g_A   + (size_t)uu * 128 + f);
    float4 b  = *(const float4*)(g_B   + (size_t)vv * 128 + f);
    float4 bs = *(const float4*)(bias + f);
    float4 h  = *(const float4*)(g_hn1 + (size_t)uu * 128 + f);
    float he0 = fmaxf(a.x + b.x + bs.x, 0.0f);
    float he1 = fmaxf(a.y + b.y + bs.y, 0.0f);
    float he2 = fmaxf(a.z + b.z + bs.z, 0.0f);
    float he3 = fmaxf(a.w + b.w + bs.w, 0.0f);
    float* base = g_agg + (size_t)vv * 256;
    atomicAdd(base + f + 0, h.x);
    atomicAdd(base + f + 1, h.y);
    atomicAdd(base + f + 2, h.z);
    atomicAdd(base + f + 3, h.w);
    atomicAdd(base + 128 + f + 0, he0);
    atomicAdd(base + 128 + f + 1, he1);
    atomicAdd(base + 128 + f + 2, he2);
    atomicAdd(base + 128 + f + 3, he3);
}

// ---------------- final edges: he2 = relu(A2[u]+B2[v]+b) -> d_out ----------------
__global__ void k_edge2(const int* __restrict__ u, const int* __restrict__ v,
                        const float* __restrict__ bias, float* __restrict__ out_he) {
    int tid = blockIdx.x * blockDim.x + threadIdx.x;
    int e = tid >> 5;
    if (e >= NE) return;
    int q = tid & 31;
    int f = q * 4;
    int uu = u[e], vv = v[e];
    float4 a  = *(const float4*)(g_A + (size_t)uu * 128 + f);
    float4 b  = *(const float4*)(g_B + (size_t)vv * 128 + f);
    float4 bs = *(const float4*)(bias + f);
    float4 r;
    r.x = fmaxf(a.x + b.x + bs.x, 0.0f);
    r.y = fmaxf(a.y + b.y + bs.y, 0.0f);
    r.z = fmaxf(a.z + b.z + bs.z, 0.0f);
    r.w = fmaxf(a.w + b.w + bs.w, 0.0f);
    *(float4*)(out_he + (size_t)e * 128 + f) = r;
}

// ---------------- tiled GEMM: out[R x 128] = op(In[R x K_DIM] @ W[K_DIM x 128] (+bias, relu)) ----
// APPLY mode: In(r,k) = k < K1 ? src1[r*K1+k] : g_agg[r*(K_DIM-K1)+(k-K1)] / max(deg,1)
// plain mode: In(r,k) = src1[r*K_DIM+k]; no bias/relu.
// BM=64, BN=128, BK=16, 256 threads, 8x4 register tile per thread.
template<int K_DIM, int K1, bool APPLY>
__global__ void k_gemm(const float* __restrict__ src1, const float* __restrict__ W,
                       const float* __restrict__ bias, float* __restrict__ out, int R) {
    __shared__ float sh_in[16][65];     // [k][row], padded
    __shared__ float sh_w[16][128];     // [k][col]
    __shared__ float sh_inv[64];

    int t = threadIdx.x;
    int row0 = blockIdx.x * 64;

    if (APPLY) {
        if (t < 64) {
            int r = row0 + t;
            float d = 1.0f;
            if (r < R) d = fmaxf((float)g_deg[r], 1.0f);
            sh_inv[t] = 1.0f / d;
        }
    }
    // (sync below before first use)

    float acc[8][4];
#pragma unroll
    for (int i = 0; i < 8; i++)
#pragma unroll
        for (int j = 0; j < 4; j++) acc[i][j] = 0.0f;

    const int lrow = t >> 2;          // 0..63
    const int lk = (t & 3) * 4;       // 0,4,8,12
    const int ty = t >> 5;            // warp-uniform -> broadcast LDS
    const int tx = t & 31;
    const int KAGG = K_DIM - K1;

    if (APPLY) __syncthreads();       // sh_inv ready

    for (int k0 = 0; k0 < K_DIM; k0 += 16) {
        // stage input tile (float4 per thread; K1 is a multiple of 4 so chunks don't straddle)
        {
            int r = row0 + lrow;
            float4 val = make_float4(0.f, 0.f, 0.f, 0.f);
            if (r < R) {
                int k = k0 + lk;
                if (!APPLY) {
                    val = *(const float4*)(src1 + (size_t)r * K_DIM + k);
                } else if (k < K1) {
                    val = *(const float4*)(src1 + (size_t)r * K1 + k);
                } else {
                    val = *(const float4*)(g_agg + (size_t)r * KAGG + (k - K1));
                    float inv = sh_inv[lrow];
                    val.x *= inv; val.y *= inv; val.z *= inv; val.w *= inv;
                }
            }
            sh_in[lk + 0][lrow] = val.x;
            sh_in[lk + 1][lrow] = val.y;
            sh_in[lk + 2][lrow] = val.z;
            sh_in[lk + 3][lrow] = val.w;
        }
        // stage weight tile (coalesced)
#pragma unroll
        for (int i = 0; i < 8; i++) {
            int idx = i * 256 + t;
            int kk = idx >> 7, j = idx & 127;
            sh_w[kk][j] = W[(size_t)(k0 + kk) * 128 + j];
        }
        __syncthreads();

#pragma unroll
        for (int kk = 0; kk < 16; kk++) {
            float a[8], bw[4];
#pragma unroll
            for (int i = 0; i < 8; i++) a[i] = sh_in[kk][ty * 8 + i];   // broadcast
#pragma unroll
            for (int j = 0; j < 4; j++) bw[j] = sh_w[kk][tx + 32 * j];  // conflict-free
#pragma unroll
            for (int i = 0; i < 8; i++)
#pragma unroll
                for (int j = 0; j < 4; j++)
                    acc[i][j] += a[i] * bw[j];
        }
        __syncthreads();
    }

#pragma unroll
    for (int i = 0; i < 8; i++) {
        int r = row0 + ty * 8 + i;
        if (r >= R) continue;
#pragma unroll
        for (int j = 0; j < 4; j++) {
            int c = tx + 32 * j;
            float vv = acc[i][j];
            if (APPLY) {
                vv += bias[c];
                vv = fmaxf(vv, 0.0f);
            }
            out[(size_t)r * 128 + c] = vv;
        }
    }
}

// ---------------- launcher ----------------
extern "C" void kernel_launch(void* const* d_in, const int* in_sizes, int n_in,
                              void* d_out, int out_size) {
    const float* nfeats = (const float*)d_in[0];
    const float* efeats = (const float*)d_in[1];
    const float* W1a_w  = (const float*)d_in[2];
    const float* W1a_b  = (const float*)d_in[3];
    const float* W1e_w  = (const float*)d_in[4];
    const float* W1e_b  = (const float*)d_in[5];
    const float* W2a_w  = (const float*)d_in[6];
    const float* W2a_b  = (const float*)d_in[7];
    const float* W2e_w  = (const float*)d_in[8];
    const float* W2e_b  = (const float*)d_in[9];
    const int*   u      = (const int*)d_in[10];
    const int*   v      = (const int*)d_in[11];

    float* out_hn = (float*)d_out;                        // [NND, 128]
    float* out_he = out_hn + (size_t)NND * HID;           // [NE, 128]

    // resolve scratch symbol addresses (host API; no allocation, capture-safe)
    void *p_hn1, *p_A, *p_B;
    cudaGetSymbolAddress(&p_hn1, g_hn1);
    cudaGetSymbolAddress(&p_A, g_A);
    cudaGetSymbolAddress(&p_B, g_B);
    float* hn1 = (float*)p_hn1;
    float* A   = (float*)p_A;
    float* B   = (float*)p_B;

    const int EDGE_BLOCKS = (NE * 32 + 255) / 256;        // 100000
    const int GEMM_BLOCKS = (NND + 63) / 64;              // 782

    // ---- layer 1 ----
    k_zero_deg<<<(NND + 255) / 256, 256>>>();
    k_zero_agg<<<2048, 256>>>((size_t)NND * 128);
    k_deg<<<(NE + 255) / 256, 256>>>(v);
    k_scatter1<<<EDGE_BLOCKS, 256>>>(nfeats, efeats, u, v);
    // hn1 = relu([nfeats | agg1/deg] @ W1a + b1a)
    k_gemm<192, 64, true><<<GEMM_BLOCKS, 256>>>(nfeats, W1a_w, W1a_b, hn1, NND);
    // A1 = hn1 @ W1e[0:128,:], B1 = hn1 @ W1e[128:256,:]
    k_gemm<128, 128, false><<<GEMM_BLOCKS, 256>>>(hn1, W1e_w, nullptr, A, NND);
    k_gemm<128, 128, false><<<GEMM_BLOCKS, 256>>>(hn1, W1e_w + 128 * 128, nullptr, B, NND);

    // ---- layer 2 ----
    k_zero_agg<<<2048, 256>>>((size_t)NND * 256);
    k_edge1<<<EDGE_BLOCKS, 256>>>(u, v, W1e_b);           // fused he1 + scatter
    // hn2 = relu([hn1 | agg2/deg] @ W2a + b2a) -> d_out
    k_gemm<384, 128, true><<<GEMM_BLOCKS, 256>>>(hn1, W2a_w, W2a_b, out_hn, NND);
    // A2 = hn2 @ W2e[0:128,:], B2 = hn2 @ W2e[128:256,:]
    k_gemm<128, 128, false><<<GEMM_BLOCKS, 256>>>(out_hn, W2e_w, nullptr, A, NND);
    k_gemm<128, 128, false><<<GEMM_BLOCKS, 256>>>(out_hn, W2e_w + 128 * 128, nullptr, B, NND);
    // he2 -> d_out
    k_edge2<<<EDGE_BLOCKS, 256>>>(u, v, W2e_b, out_he);
}

// round 3
// speedup vs baseline: 1.6780x; 1.6780x over previous
#include <cuda_runtime.h>
#include <cstdint>
#include <cstddef>

#define NND 50000
#define NE  800000
#define HID 128

// ---------------- scratch (static device globals; no allocation) ----------------
__device__ float g_agg[(size_t)NND * 256];   // layer1 uses stride 128, layer2 stride 256
__device__ int   g_deg[NND];
__device__ int   g_start[NND + 1];
__device__ int   g_fill[NND];
__device__ int   g_csr_e[NE];
__device__ int   g_csr_u[NE];
__device__ float g_hn1[(size_t)NND * HID];
__device__ float g_A[(size_t)NND * HID];
__device__ float g_B[(size_t)NND * HID];

// ---------------- degree + CSR build ----------------
__global__ void k_zero_deg() {
    int i = blockIdx.x * blockDim.x + threadIdx.x;
    if (i < NND) g_deg[i] = 0;
}

__global__ void k_deg(const int* __restrict__ v) {
    int i = blockIdx.x * blockDim.x + threadIdx.x;
    if (i < NE) atomicAdd(&g_deg[v[i]], 1);
}

// single-block exclusive scan over g_deg -> g_start, g_fill
__global__ void k_scan() {
    __shared__ int sh[1024];
    __shared__ int carry;
    int t = threadIdx.x;
    if (t == 0) carry = 0;
    __syncthreads();
    for (int base = 0; base < NND; base += 1024) {
        int i = base + t;
        int x = (i < NND) ? g_deg[i] : 0;
        sh[t] = x;
        __syncthreads();
#pragma unroll
        for (int off = 1; off < 1024; off <<= 1) {
            int tmp = (t >= off) ? sh[t - off] : 0;
            __syncthreads();
            sh[t] += tmp;
            __syncthreads();
        }
        int excl = sh[t] - x + carry;
        if (i < NND) { g_start[i] = excl; g_fill[i] = excl; }
        __syncthreads();
        if (t == 0) carry += sh[1023];
        __syncthreads();
    }
    if (t == 0) g_start[NND] = carry;   // == NE
}

__global__ void k_bin(const int* __restrict__ u, const int* __restrict__ v) {
    int e = blockIdx.x * blockDim.x + threadIdx.x;
    if (e >= NE) return;
    int pos = atomicAdd(&g_fill[v[e]], 1);
    g_csr_e[pos] = e;
    g_csr_u[pos] = u[e];
}

// ---------------- layer-1 aggregation: g_agg[n][0:128] = mean over in-edges of [nf[u]|ef[e]] ----
__global__ void k_agg1(const float* __restrict__ nf, const float* __restrict__ ef) {
    int w = (blockIdx.x * blockDim.x + threadIdx.x) >> 5;
    if (w >= NND) return;
    int q = threadIdx.x & 31;                 // 32 lanes/node, 4 floats/lane
    int s = g_start[w], e_end = g_start[w + 1];
    float4 acc = make_float4(0.f, 0.f, 0.f, 0.f);
    for (int i = s; i < e_end; i++) {
        const float* src;
        if (q < 16) { int uu = g_csr_u[i]; src = nf + (size_t)uu * 64 + q * 4; }
        else        { int ee = g_csr_e[i]; src = ef + (size_t)ee * 64 + (q - 16) * 4; }
        float4 val = *(const float4*)src;
        acc.x += val.x; acc.y += val.y; acc.z += val.z; acc.w += val.w;
    }
    float inv = 1.0f / fmaxf((float)(e_end - s), 1.0f);
    acc.x *= inv; acc.y *= inv; acc.z *= inv; acc.w *= inv;
    *(float4*)(g_agg + (size_t)w * 128 + q * 4) = acc;
}

// ---------------- layer-2 aggregation (he1 fused):
// g_agg[n][0:128]   = mean over in-edges of hn1[u]
// g_agg[n][128:256] = mean over in-edges of relu(A1[u] + B1[n] + bias)
__global__ void k_agg2(const float* __restrict__ bias) {
    int w = (blockIdx.x * blockDim.x + threadIdx.x) >> 5;
    if (w >= NND) return;
    int q = threadIdx.x & 31;
    int f = q * 4;
    int s = g_start[w], e_end = g_start[w + 1];
    float4 b  = *(const float4*)(g_B + (size_t)w * 128 + f);
    float4 bs = *(const float4*)(bias + f);
    b.x += bs.x; b.y += bs.y; b.z += bs.z; b.w += bs.w;
    float4 ah = make_float4(0.f, 0.f, 0.f, 0.f);
    float4 ae = make_float4(0.f, 0.f, 0.f, 0.f);
    for (int i = s; i < e_end; i++) {
        int uu = g_csr_u[i];
        float4 h = *(const float4*)(g_hn1 + (size_t)uu * 128 + f);
        float4 a = *(const float4*)(g_A   + (size_t)uu * 128 + f);
        ah.x += h.x; ah.y += h.y; ah.z += h.z; ah.w += h.w;
        ae.x += fmaxf(a.x + b.x, 0.f);
        ae.y += fmaxf(a.y + b.y, 0.f);
        ae.z += fmaxf(a.z + b.z, 0.f);
        ae.w += fmaxf(a.w + b.w, 0.f);
    }
    float inv = 1.0f / fmaxf((float)(e_end - s), 1.0f);
    float* base = g_agg + (size_t)w * 256;
    *(float4*)(base + f) = make_float4(ah.x * inv, ah.y * inv, ah.z * inv, ah.w * inv);
    *(float4*)(base + 128 + f) = make_float4(ae.x * inv, ae.y * inv, ae.z * inv, ae.w * inv);
}

// ---------------- final edges: he2 = relu(A2[u]+B2[v]+b) -> d_out ----------------
__global__ void k_edge2(const int* __restrict__ u, const int* __restrict__ v,
                        const float* __restrict__ bias, float* __restrict__ out_he) {
    int tid = blockIdx.x * blockDim.x + threadIdx.x;
    int e = tid >> 5;
    if (e >= NE) return;
    int q = tid & 31;
    int f = q * 4;
    int uu = u[e], vv = v[e];
    float4 a  = *(const float4*)(g_A + (size_t)uu * 128 + f);
    float4 b  = *(const float4*)(g_B + (size_t)vv * 128 + f);
    float4 bs = *(const float4*)(bias + f);
    float4 r;
    r.x = fmaxf(a.x + b.x + bs.x, 0.0f);
    r.y = fmaxf(a.y + b.y + bs.y, 0.0f);
    r.z = fmaxf(a.z + b.z + bs.z, 0.0f);
    r.w = fmaxf(a.w + b.w + bs.w, 0.0f);
    *(float4*)(out_he + (size_t)e * 128 + f) = r;
}

// ---------------- tiled GEMM: out[R x 128] = op(In[R x K_DIM] @ W[K_DIM x 128] (+bias, relu)) ----
// APPLY mode: In(r,k) = k < K1 ? src1[r*K1+k] : g_agg[r*(K_DIM-K1)+(k-K1)]  (agg pre-averaged)
// plain mode: In(r,k) = src1[r*K_DIM+k]; no bias/relu.
// BM=64, BN=128, BK=16, 256 threads, 8x4 register tile per thread.
template<int K_DIM, int K1, bool APPLY>
__global__ void k_gemm(const float* __restrict__ src1, const float* __restrict__ W,
                       const float* __restrict__ bias, float* __restrict__ out, int R) {
    __shared__ float sh_in[16][65];     // [k][row], padded
    __shared__ float sh_w[16][128];     // [k][col]

    int t = threadIdx.x;
    int row0 = blockIdx.x * 64;

    float acc[8][4];
#pragma unroll
    for (int i = 0; i < 8; i++)
#pragma unroll
        for (int j = 0; j < 4; j++) acc[i][j] = 0.0f;

    const int lrow = t >> 2;          // 0..63
    const int lk = (t & 3) * 4;       // 0,4,8,12
    const int ty = t >> 5;            // warp-uniform -> broadcast LDS
    const int tx = t & 31;
    const int KAGG = K_DIM - K1;

    for (int k0 = 0; k0 < K_DIM; k0 += 16) {
        // stage input tile (float4 per thread; K1 % 4 == 0 so chunks don't straddle)
        {
            int r = row0 + lrow;
            float4 val = make_float4(0.f, 0.f, 0.f, 0.f);
            if (r < R) {
                int k = k0 + lk;
                if (!APPLY) {
                    val = *(const float4*)(src1 + (size_t)r * K_DIM + k);
                } else if (k < K1) {
                    val = *(const float4*)(src1 + (size_t)r * K1 + k);
                } else {
                    val = *(const float4*)(g_agg + (size_t)r * KAGG + (k - K1));
                }
            }
            sh_in[lk + 0][lrow] = val.x;
            sh_in[lk + 1][lrow] = val.y;
            sh_in[lk + 2][lrow] = val.z;
            sh_in[lk + 3][lrow] = val.w;
        }
        // stage weight tile (coalesced)
#pragma unroll
        for (int i = 0; i < 8; i++) {
            int idx = i * 256 + t;
            int kk = idx >> 7, j = idx & 127;
            sh_w[kk][j] = W[(size_t)(k0 + kk) * 128 + j];
        }
        __syncthreads();

#pragma unroll
        for (int kk = 0; kk < 16; kk++) {
            float a[8], bw[4];
#pragma unroll
            for (int i = 0; i < 8; i++) a[i] = sh_in[kk][ty * 8 + i];   // broadcast
#pragma unroll
            for (int j = 0; j < 4; j++) bw[j] = sh_w[kk][tx + 32 * j];  // conflict-free
#pragma unroll
            for (int i = 0; i < 8; i++)
#pragma unroll
                for (int j = 0; j < 4; j++)
                    acc[i][j] += a[i] * bw[j];
        }
        __syncthreads();
    }

#pragma unroll
    for (int i = 0; i < 8; i++) {
        int r = row0 + ty * 8 + i;
        if (r >= R) continue;
#pragma unroll
        for (int j = 0; j < 4; j++) {
            int c = tx + 32 * j;
            float vv = acc[i][j];
            if (APPLY) {
                vv += bias[c];
                vv = fmaxf(vv, 0.0f);
            }
            out[(size_t)r * 128 + c] = vv;
        }
    }
}

// ---------------- launcher ----------------
extern "C" void kernel_launch(void* const* d_in, const int* in_sizes, int n_in,
                              void* d_out, int out_size) {
    const float* nfeats = (const float*)d_in[0];
    const float* efeats = (const float*)d_in[1];
    const float* W1a_w  = (const float*)d_in[2];
    const float* W1a_b  = (const float*)d_in[3];
    const float* W1e_w  = (const float*)d_in[4];
    const float* W1e_b  = (const float*)d_in[5];
    const float* W2a_w  = (const float*)d_in[6];
    const float* W2a_b  = (const float*)d_in[7];
    const float* W2e_w  = (const float*)d_in[8];
    const float* W2e_b  = (const float*)d_in[9];
    const int*   u      = (const int*)d_in[10];
    const int*   v      = (const int*)d_in[11];

    float* out_hn = (float*)d_out;                        // [NND, 128]
    float* out_he = out_hn + (size_t)NND * HID;           // [NE, 128]

    void *p_hn1, *p_A, *p_B;
    cudaGetSymbolAddress(&p_hn1, g_hn1);
    cudaGetSymbolAddress(&p_A, g_A);
    cudaGetSymbolAddress(&p_B, g_B);
    float* hn1 = (float*)p_hn1;
    float* A   = (float*)p_A;
    float* B   = (float*)p_B;

    const int EDGE_BLOCKS = (NE * 32 + 255) / 256;        // warp per edge (k_edge2)
    const int NODE_WARPS  = (NND * 32 + 255) / 256;       // warp per node (agg)
    const int GEMM_BLOCKS = (NND + 63) / 64;              // 782

    // ---- CSR build ----
    k_zero_deg<<<(NND + 255) / 256, 256>>>();
    k_deg<<<(NE + 255) / 256, 256>>>(v);
    k_scan<<<1, 1024>>>();
    k_bin<<<(NE + 255) / 256, 256>>>(u, v);

    // ---- layer 1 ----
    k_agg1<<<NODE_WARPS, 256>>>(nfeats, efeats);
    k_gemm<192, 64, true><<<GEMM_BLOCKS, 256>>>(nfeats, W1a_w, W1a_b, hn1, NND);
    k_gemm<128, 128, false><<<GEMM_BLOCKS, 256>>>(hn1, W1e_w, nullptr, A, NND);
    k_gemm<128, 128, false><<<GEMM_BLOCKS, 256>>>(hn1, W1e_w + 128 * 128, nullptr, B, NND);

    // ---- layer 2 ----
    k_agg2<<<NODE_WARPS, 256>>>(W1e_b);                   // fused he1 + mean aggregation
    k_gemm<384, 128, true><<<GEMM_BLOCKS, 256>>>(hn1, W2a_w, W2a_b, out_hn, NND);
    k_gemm<128, 128, false><<<GEMM_BLOCKS, 256>>>(out_hn, W2e_w, nullptr, A, NND);
    k_gemm<128, 128, false><<<GEMM_BLOCKS, 256>>>(out_hn, W2e_w + 128 * 128, nullptr, B, NND);
    k_edge2<<<EDGE_BLOCKS, 256>>>(u, v, W2e_b, out_he);
}

// round 11
// speedup vs baseline: 2.2606x; 1.3472x over previous
#include <cuda_runtime.h>
#include <cuda_bf16.h>
#include <cstdint>
#include <cstddef>

#define NND 50000
#define NE  800000

// ---------------- scratch (static device globals; no allocation) ----------------
__device__ int   g_deg[NND];
__device__ int   g_start[NND + 1];
__device__ int   g_fill[NND];
__device__ int   g_csr_e[NE];
__device__ int   g_csr_u[NE];
__device__ float g_hn1[(size_t)NND * 128];
__device__ float g_A[(size_t)NND * 128];
__device__ float g_B[(size_t)NND * 128];
// bf16-split GEMM inputs
__device__ __nv_bfloat16 g_x1h[(size_t)NND * 192];
__device__ __nv_bfloat16 g_x1l[(size_t)NND * 192];
__device__ __nv_bfloat16 g_x2h[(size_t)NND * 384];
__device__ __nv_bfloat16 g_x2l[(size_t)NND * 384];
__device__ __nv_bfloat16 g_xoh[(size_t)NND * 128];
__device__ __nv_bfloat16 g_xol[(size_t)NND * 128];
// transposed split weights: [n=128, k=K] K-major, packed segments
__device__ __nv_bfloat16 g_wth[128 * 1088];
__device__ __nv_bfloat16 g_wtl[128 * 1088];
// segment offsets (elements)
#define O_W1A   0
#define O_W1ET  24576
#define O_W1EB  40960
#define O_W2A   57344
#define O_W2ET  106496
#define O_W2EB  122880

// ---------------- helpers ----------------
__device__ __forceinline__ uint32_t smem_u32(const void* p) {
    uint32_t a;
    asm("{ .reg .u64 t; cvta.to.shared.u64 t, %1; cvt.u32.u64 %0, t; }" : "=r"(a) : "l"(p));
    return a;
}
#define SWZ(o) ((o) ^ (((o) >> 3) & 0x70))

__device__ __forceinline__ void ldm4(uint32_t* r, uint32_t addr) {
    asm volatile("ldmatrix.sync.aligned.m8n8.x4.shared.b16 {%0,%1,%2,%3}, [%4];"
                 : "=r"(r[0]), "=r"(r[1]), "=r"(r[2]), "=r"(r[3]) : "r"(addr));
}
__device__ __forceinline__ void mma16816(float* c, const uint32_t* a, uint32_t b0, uint32_t b1) {
    asm volatile("mma.sync.aligned.m16n8k16.row.col.f32.bf16.bf16.f32 "
                 "{%0,%1,%2,%3}, {%4,%5,%6,%7}, {%8,%9}, {%0,%1,%2,%3};"
                 : "+f"(c[0]), "+f"(c[1]), "+f"(c[2]), "+f"(c[3])
                 : "r"(a[0]), "r"(a[1]), "r"(a[2]), "r"(a[3]), "r"(b0), "r"(b1));
}

__device__ __forceinline__ void bsplit(float x, __nv_bfloat16& h, __nv_bfloat16& l) {
    h = __float2bfloat16(x);
    l = __float2bfloat16(x - __bfloat162float(h));
}
__device__ __forceinline__ void store_split4(__nv_bfloat16* oh, __nv_bfloat16* ol,
                                             size_t base, float4 v) {
    __nv_bfloat16 h0, h1, h2, h3, l0, l1, l2, l3;
    bsplit(v.x, h0, l0); bsplit(v.y, h1, l1); bsplit(v.z, h2, l2); bsplit(v.w, h3, l3);
    __nv_bfloat162 a = {h0, h1}, b = {h2, h3}, c = {l0, l1}, d = {l2, l3};
    *(__nv_bfloat162*)(oh + base) = a;
    *(__nv_bfloat162*)(oh + base + 2) = b;
    *(__nv_bfloat162*)(ol + base) = c;
    *(__nv_bfloat162*)(ol + base + 2) = d;
}
__device__ __forceinline__ void store_split2(__nv_bfloat16* oh, __nv_bfloat16* ol,
                                             size_t base, float v0, float v1) {
    __nv_bfloat16 h0, h1, l0, l1;
    bsplit(v0, h0, l0); bsplit(v1, h1, l1);
    __nv_bfloat162 a = {h0, h1}, c = {l0, l1};
    *(__nv_bfloat162*)(oh + base) = a;
    *(__nv_bfloat162*)(ol + base) = c;
}

// ---------------- degree + CSR build ----------------
__global__ void k_zero_deg() {
    int i = blockIdx.x * blockDim.x + threadIdx.x;
    if (i < NND) g_deg[i] = 0;
}
__global__ void k_deg(const int* __restrict__ v) {
    int i = blockIdx.x * blockDim.x + threadIdx.x;
    if (i < NE) atomicAdd(&g_deg[v[i]], 1);
}
__global__ void k_scan() {
    __shared__ int sh[1024];
    __shared__ int carry;
    int t = threadIdx.x;
    if (t == 0) carry = 0;
    __syncthreads();
    for (int base = 0; base < NND; base += 1024) {
        int i = base + t;
        int x = (i < NND) ? g_deg[i] : 0;
        sh[t] = x;
        __syncthreads();
#pragma unroll
        for (int off = 1; off < 1024; off <<= 1) {
            int tmp = (t >= off) ? sh[t - off] : 0;
            __syncthreads();
            sh[t] += tmp;
            __syncthreads();
        }
        int excl = sh[t] - x + carry;
        if (i < NND) { g_start[i] = excl; g_fill[i] = excl; }
        __syncthreads();
        if (t == 0) carry += sh[1023];
        __syncthreads();
    }
    if (t == 0) g_start[NND] = carry;
}
__global__ void k_bin(const int* __restrict__ u, const int* __restrict__ v) {
    int e = blockIdx.x * blockDim.x + threadIdx.x;
    if (e >= NE) return;
    int pos = atomicAdd(&g_fill[v[e]], 1);
    g_csr_e[pos] = e;
    g_csr_u[pos] = u[e];
}

// ---------------- prep: nfeats -> X1[:,0:64] split; weights -> transposed split ----------------
__global__ void k_prep(const float* __restrict__ nf, const float* __restrict__ W1a,
                       const float* __restrict__ W1e, const float* __restrict__ W2a,
                       const float* __restrict__ W2e) {
    int id = blockIdx.x * blockDim.x + threadIdx.x;
    if (id < NND * 64) {
        int r = id >> 6, c = id & 63;
        __nv_bfloat16 h, l;
        bsplit(nf[id], h, l);
        g_x1h[(size_t)r * 192 + c] = h;
        g_x1l[(size_t)r * 192 + c] = l;
        return;
    }
    id -= NND * 64;
    const float* W; int K, o;
    if      (id < 24576)  { W = W1a;           K = 192; o = O_W1A; }
    else if (id < 40960)  { W = W1e;           K = 128; o = O_W1ET; id -= 24576; }
    else if (id < 57344)  { W = W1e + 16384;   K = 128; o = O_W1EB; id -= 40960; }
    else if (id < 106496) { W = W2a;           K = 384; o = O_W2A;  id -= 57344; }
    else if (id < 122880) { W = W2e;           K = 128; o = O_W2ET; id -= 106496; }
    else if (id < 139264) { W = W2e + 16384;   K = 128; o = O_W2EB; id -= 122880; }
    else return;
    int k = id >> 7, n = id & 127;
    __nv_bfloat16 h, l;
    bsplit(W[(size_t)k * 128 + n], h, l);
    g_wth[o + n * K + k] = h;
    g_wtl[o + n * K + k] = l;
}

// ---------------- layer-1 aggregation -> bf16 split into X1[:,64:192] ----------------
__global__ void k_agg1(const float* __restrict__ nf, const float* __restrict__ ef) {
    int w = (blockIdx.x * blockDim.x + threadIdx.x) >> 5;
    if (w >= NND) return;
    int q = threadIdx.x & 31;
    int s = g_start[w], e_end = g_start[w + 1];
    float4 acc = make_float4(0.f, 0.f, 0.f, 0.f);
    for (int i = s; i < e_end; i++) {
        const float* src;
        if (q < 16) { int uu = g_csr_u[i]; src = nf + (size_t)uu * 64 + q * 4; }
        else        { int ee = g_csr_e[i]; src = ef + (size_t)ee * 64 + (q - 16) * 4; }
        float4 val = *(const float4*)src;
        acc.x += val.x; acc.y += val.y; acc.z += val.z; acc.w += val.w;
    }
    float inv = 1.0f / fmaxf((float)(e_end - s), 1.0f);
    acc.x *= inv; acc.y *= inv; acc.z *= inv; acc.w *= inv;
    store_split4(g_x1h, g_x1l, (size_t)w * 192 + 64 + q * 4, acc);
}

// ---------------- layer-2 aggregation (he1 fused) -> bf16 split into X2[:,128:384] ----------------
__global__ void k_agg2(const float* __restrict__ bias) {
    int w = (blockIdx.x * blockDim.x + threadIdx.x) >> 5;
    if (w >= NND) return;
    int q = threadIdx.x & 31;
    int f = q * 4;
    int s = g_start[w], e_end = g_start[w + 1];
    float4 b  = *(const float4*)(g_B + (size_t)w * 128 + f);
    float4 bs = *(const float4*)(bias + f);
    b.x += bs.x; b.y += bs.y; b.z += bs.z; b.w += bs.w;
    float4 ah = make_float4(0.f, 0.f, 0.f, 0.f);
    float4 ae = make_float4(0.f, 0.f, 0.f, 0.f);
    for (int i = s; i < e_end; i++) {
        int uu = g_csr_u[i];
        float4 h = *(const float4*)(g_hn1 + (size_t)uu * 128 + f);
        float4 a = *(const float4*)(g_A   + (size_t)uu * 128 + f);
        ah.x += h.x; ah.y += h.y; ah.z += h.z; ah.w += h.w;
        ae.x += fmaxf(a.x + b.x, 0.f);
        ae.y += fmaxf(a.y + b.y, 0.f);
        ae.z += fmaxf(a.z + b.z, 0.f);
        ae.w += fmaxf(a.w + b.w, 0.f);
    }
    float inv = 1.0f / fmaxf((float)(e_end - s), 1.0f);
    ah.x *= inv; ah.y *= inv; ah.z *= inv; ah.w *= inv;
    ae.x *= inv; ae.y *= inv; ae.z *= inv; ae.w *= inv;
    store_split4(g_x2h, g_x2l, (size_t)w * 384 + 128 + f, ah);
    store_split4(g_x2h, g_x2l, (size_t)w * 384 + 256 + f, ae);
}

// ---------------- final edges: he2 = relu(A2[u]+B2[v]+b) -> d_out ----------------
__global__ void k_edge2(const int* __restrict__ u, const int* __restrict__ v,
                        const float* __restrict__ bias, float* __restrict__ out_he) {
    int tid = blockIdx.x * blockDim.x + threadIdx.x;
    int e = tid >> 5;
    if (e >= NE) return;
    int q = tid & 31;
    int f = q * 4;
    int uu = u[e], vv = v[e];
    float4 a  = *(const float4*)(g_A + (size_t)uu * 128 + f);
    float4 b  = *(const float4*)(g_B + (size_t)vv * 128 + f);
    float4 bs = *(const float4*)(bias + f);
    float4 r;
    r.x = fmaxf(a.x + b.x + bs.x, 0.0f);
    r.y = fmaxf(a.y + b.y + bs.y, 0.0f);
    r.z = fmaxf(a.z + b.z + bs.z, 0.0f);
    r.w = fmaxf(a.w + b.w + bs.w, 0.0f);
    *(float4*)(out_he + (size_t)e * 128 + f) = r;
}

// ---------------- warp-MMA GEMM: out[M,128] = relu?(X @ Wt^T + bias) ----------------
// X split (Xh+Xl) [R, K_DIM] row stride ldx; Wt split [128, K_DIM] K-major.
// mma.sync m16n8k16 bf16; 3-term split (hh + hl + lh) -> ~fp32 accuracy.
// Block: 256 threads = 8 warps as 4(M) x 2(N); warp tile 32x64; block tile 128x128.
template<int K_DIM, bool RELU, bool BF16OUT>
__global__ void __launch_bounds__(256, 1)
k_mma(const __nv_bfloat16* __restrict__ Xh, const __nv_bfloat16* __restrict__ Xl, int ldx,
      const __nv_bfloat16* __restrict__ Wh, const __nv_bfloat16* __restrict__ Wl,
      const float* __restrict__ bias, float* __restrict__ out32,
      __nv_bfloat16* __restrict__ oh, __nv_bfloat16* __restrict__ ol, int ldo, int R)
{
    extern __shared__ char sm[];
    const int AH = 0, AL = 16384, BH = 32768, BL = 49152;
    uint32_t sb = smem_u32(sm);
    int t = threadIdx.x, wid = t >> 5, lane = t & 31;
    int row0 = blockIdx.x * 128;
    int m_base = (wid & 3) * 32;
    int n_base = (wid >> 2) * 64;

    float acc[2][8][4];
#pragma unroll
    for (int i = 0; i < 2; i++)
#pragma unroll
        for (int j = 0; j < 8; j++)
#pragma unroll
            for (int q = 0; q < 4; q++) acc[i][j][q] = 0.0f;

    const int g = lane >> 3, r8 = lane & 7;
    const int a_ro = ((g & 1) << 3) + r8;      // A: row offset within 16-row tile
    const int a_ko = (g >> 1) << 3;            // A: k offset within 16-k step
    const int b_ro = ((g >> 1) << 3) + r8;     // B: n offset within 16-n pair
    const int b_ko = (g & 1) << 3;             // B: k offset within 16-k step

    for (int kc = 0; kc < K_DIM / 64; kc++) {
        int kc0 = kc * 64;
        // ---- stage A(hi/lo) rows 128 x 64k and B(hi/lo) 128n x 64k, SW128 swizzled ----
#pragma unroll
        for (int i = 0; i < 4; i++) {
            int idx = t + i * 256;
            int row = idx >> 3, j = idx & 7;
            uint4 vh = make_uint4(0, 0, 0, 0), vl = make_uint4(0, 0, 0, 0);
            if (row0 + row < R) {
                size_t go = (size_t)(row0 + row) * ldx + kc0 + j * 8;
                vh = *(const uint4*)(Xh + go);
                vl = *(const uint4*)(Xl + go);
            }
            uint32_t so = SWZ(row * 128 + j * 16);
            *(uint4*)(sm + AH + so) = vh;
            *(uint4*)(sm + AL + so) = vl;
            size_t wo = (size_t)row * K_DIM + kc0 + j * 8;
            *(uint4*)(sm + BH + so) = *(const uint4*)(Wh + wo);
            *(uint4*)(sm + BL + so) = *(const uint4*)(Wl + wo);
        }
        __syncthreads();

        // ---- compute: 4 k-steps of 16 ----
#pragma unroll
        for (int ks = 0; ks < 4; ks++) {
            int k0 = ks * 16;
            uint32_t ah[2][4], al[2][4];
#pragma unroll
            for (int mt = 0; mt < 2; mt++) {
                uint32_t off = SWZ((m_base + mt * 16 + a_ro) * 128 + (k0 + a_ko) * 2);
                ldm4(ah[mt], sb + AH + off);
                ldm4(al[mt], sb + AL + off);
            }
#pragma unroll
            for (int np = 0; np < 4; np++) {
                uint32_t boff = SWZ((n_base + np * 16 + b_ro) * 128 + (k0 + b_ko) * 2);
                uint32_t bh[4], bl[4];
                ldm4(bh, sb + BH + boff);
                ldm4(bl, sb + BL + boff);
#pragma unroll
                for (int mt = 0; mt < 2; mt++) {
                    mma16816(acc[mt][np * 2], ah[mt], bh[0], bh[1]);
                    mma16816(acc[mt][np * 2], ah[mt], bl[0], bl[1]);
                    mma16816(acc[mt][np * 2], al[mt], bh[0], bh[1]);
                    mma16816(acc[mt][np * 2 + 1], ah[mt], bh[2], bh[3]);
                    mma16816(acc[mt][np * 2 + 1], ah[mt], bl[2], bl[3]);
                    mma16816(acc[mt][np * 2 + 1], al[mt], bh[2], bh[3]);
                }
            }
        }
        __syncthreads();
    }

    // ---- epilogue ----
    const int rl = lane >> 2, cl = (lane & 3) * 2;
#pragma unroll
    for (int mt = 0; mt < 2; mt++) {
#pragma unroll
        for (int h = 0; h < 2; h++) {
            int row = row0 + m_base + mt * 16 + h * 8 + rl;
            if (row >= R) continue;
#pragma unroll
            for (int nt = 0; nt < 8; nt++) {
                int col = n_base + nt * 8 + cl;
                float v0 = acc[mt][nt][h * 2 + 0];
                float v1 = acc[mt][nt][h * 2 + 1];
                if (RELU) {
                    float2 bs = *(const float2*)(bias + col);
                    v0 = fmaxf(v0 + bs.x, 0.f);
                    v1 = fmaxf(v1 + bs.y, 0.f);
                }
                float2 vv = {v0, v1};
                *(float2*)(out32 + (size_t)row * 128 + col) = vv;
                if (BF16OUT) store_split2(oh, ol, (size_t)row * ldo + col, v0, v1);
            }
        }
    }
}

// ---------------- launcher ----------------
extern "C" void kernel_launch(void* const* d_in, const int* in_sizes, int n_in,
                              void* d_out, int out_size) {
    const float* nfeats = (const float*)d_in[0];
    const float* efeats = (const float*)d_in[1];
    const float* W1a_w  = (const float*)d_in[2];
    const float* W1a_b  = (const float*)d_in[3];
    const float* W1e_w  = (const float*)d_in[4];
    const float* W1e_b  = (const float*)d_in[5];
    const float* W2a_w  = (const float*)d_in[6];
    const float* W2a_b  = (const float*)d_in[7];
    const float* W2e_w  = (const float*)d_in[8];
    const float* W2e_b  = (const float*)d_in[9];
    const int*   u      = (const int*)d_in[10];
    const int*   v      = (const int*)d_in[11];

    float* out_hn = (float*)d_out;                        // [NND, 128]
    float* out_he = out_hn + (size_t)NND * 128;           // [NE, 128]

    void *p;
    cudaGetSymbolAddress(&p, g_hn1); float* hn1 = (float*)p;
    cudaGetSymbolAddress(&p, g_A);   float* A   = (float*)p;
    cudaGetSymbolAddress(&p, g_B);   float* B   = (float*)p;
    cudaGetSymbolAddress(&p, g_x1h); __nv_bfloat16* x1h = (__nv_bfloat16*)p;
    cudaGetSymbolAddress(&p, g_x1l); __nv_bfloat16* x1l = (__nv_bfloat16*)p;
    cudaGetSymbolAddress(&p, g_x2h); __nv_bfloat16* x2h = (__nv_bfloat16*)p;
    cudaGetSymbolAddress(&p, g_x2l); __nv_bfloat16* x2l = (__nv_bfloat16*)p;
    cudaGetSymbolAddress(&p, g_xoh); __nv_bfloat16* xoh = (__nv_bfloat16*)p;
    cudaGetSymbolAddress(&p, g_xol); __nv_bfloat16* xol = (__nv_bfloat16*)p;
    cudaGetSymbolAddress(&p, g_wth); __nv_bfloat16* wth = (__nv_bfloat16*)p;
    cudaGetSymbolAddress(&p, g_wtl); __nv_bfloat16* wtl = (__nv_bfloat16*)p;

    const int SMG = 65536;
    cudaFuncSetAttribute(k_mma<192, true, true>,   cudaFuncAttributeMaxDynamicSharedMemorySize, SMG);
    cudaFuncSetAttribute(k_mma<384, true, true>,   cudaFuncAttributeMaxDynamicSharedMemorySize, SMG);
    cudaFuncSetAttribute(k_mma<128, false, false>, cudaFuncAttributeMaxDynamicSharedMemorySize, SMG);

    const int EDGE_BLOCKS = (NE * 32 + 255) / 256;
    const int NODE_WARPS  = (NND * 32 + 255) / 256;
    const int GB = (NND + 127) / 128;                     // 391
    const int PREP = (NND * 64 + 139264 + 255) / 256;

    // ---- CSR build + prep ----
    k_zero_deg<<<(NND + 255) / 256, 256>>>();
    k_deg<<<(NE + 255) / 256, 256>>>(v);
    k_scan<<<1, 1024>>>();
    k_bin<<<(NE + 255) / 256, 256>>>(u, v);
    k_prep<<<PREP, 256>>>(nfeats, W1a_w, W1e_w, W2a_w, W2e_w);

    // ---- layer 1 ----
    k_agg1<<<NODE_WARPS, 256>>>(nfeats, efeats);
    // hn1 = relu(X1 @ W1a + b); bf16-split hn1 into X2[:,0:128]
    k_mma<192, true, true><<<GB, 256, SMG>>>(x1h, x1l, 192, wth + O_W1A, wtl + O_W1A,
                                             W1a_b, hn1, x2h, x2l, 384, NND);
    // A1 = hn1 @ W1e_top, B1 = hn1 @ W1e_bot
    k_mma<128, false, false><<<GB, 256, SMG>>>(x2h, x2l, 384, wth + O_W1ET, wtl + O_W1ET,
                                               nullptr, A, nullptr, nullptr, 0, NND);
    k_mma<128, false, false><<<GB, 256, SMG>>>(x2h, x2l, 384, wth + O_W1EB, wtl + O_W1EB,
                                               nullptr, B, nullptr, nullptr, 0, NND);

    // ---- layer 2 ----
    k_agg2<<<NODE_WARPS, 256>>>(W1e_b);
    // hn2 = relu(X2 @ W2a + b) -> d_out; bf16-split into XO
    k_mma<384, true, true><<<GB, 256, SMG>>>(x2h, x2l, 384, wth + O_W2A, wtl + O_W2A,
                                             W2a_b, out_hn, xoh, xol, 128, NND);
    // A2/B2 = hn2 @ W2e_top/bot
    k_mma<128, false, false><<<GB, 256, SMG>>>(xoh, xol, 128, wth + O_W2ET, wtl + O_W2ET,
                                               nullptr, A, nullptr, nullptr, 0, NND);
    k_mma<128, false, false><<<GB, 256, SMG>>>(xoh, xol, 128, wth + O_W2EB, wtl + O_W2EB,
                                               nullptr, B, nullptr, nullptr, 0, NND);
    k_edge2<<<EDGE_BLOCKS, 256>>>(u, v, W2e_b, out_he);
}

// round 15
// speedup vs baseline: 2.7896x; 1.2340x over previous
#include <cuda_runtime.h>
#include <cuda_bf16.h>
#include <cstdint>
#include <cstddef>

#define NND 50000
#define NE  800000
#define NB_SCAN 98   // ceil(50000/512)

// ---------------- scratch (static device globals; no allocation) ----------------
__device__ int   g_deg[NND];
__device__ int   g_start[NND + 1];
__device__ int   g_fill[NND];
__device__ int   g_bsum[NB_SCAN];
__device__ int   g_boff[NB_SCAN];
__device__ int2  g_csr[NE];          // (edge, src)
__device__ float g_hn1[(size_t)NND * 128];
__device__ float g_A[(size_t)NND * 128];
__device__ float g_B[(size_t)NND * 128];
// bf16-split GEMM inputs
__device__ __nv_bfloat16 g_x1h[(size_t)NND * 192];
__device__ __nv_bfloat16 g_x1l[(size_t)NND * 192];
__device__ __nv_bfloat16 g_x2h[(size_t)NND * 384];
__device__ __nv_bfloat16 g_x2l[(size_t)NND * 384];
__device__ __nv_bfloat16 g_xoh[(size_t)NND * 128];
__device__ __nv_bfloat16 g_xol[(size_t)NND * 128];
// transposed split weights: [n=128, k=K] K-major, packed segments
__device__ __nv_bfloat16 g_wth[128 * 1088];
__device__ __nv_bfloat16 g_wtl[128 * 1088];
// segment offsets (elements)
#define O_W1A   0
#define O_W1ET  24576
#define O_W1EB  40960
#define O_W2A   57344
#define O_W2ET  106496
#define O_W2EB  122880

// ---------------- helpers ----------------
__device__ __forceinline__ uint32_t smem_u32(const void* p) {
    uint32_t a;
    asm("{ .reg .u64 t; cvta.to.shared.u64 t, %1; cvt.u32.u64 %0, t; }" : "=r"(a) : "l"(p));
    return a;
}
#define SWZ(o) ((o) ^ (((o) >> 3) & 0x70))

__device__ __forceinline__ void ldm4(uint32_t* r, uint32_t addr) {
    asm volatile("ldmatrix.sync.aligned.m8n8.x4.shared.b16 {%0,%1,%2,%3}, [%4];"
                 : "=r"(r[0]), "=r"(r[1]), "=r"(r[2]), "=r"(r[3]) : "r"(addr));
}
__device__ __forceinline__ void mma16816(float* c, const uint32_t* a, uint32_t b0, uint32_t b1) {
    asm volatile("mma.sync.aligned.m16n8k16.row.col.f32.bf16.bf16.f32 "
                 "{%0,%1,%2,%3}, {%4,%5,%6,%7}, {%8,%9}, {%0,%1,%2,%3};"
                 : "+f"(c[0]), "+f"(c[1]), "+f"(c[2]), "+f"(c[3])
                 : "r"(a[0]), "r"(a[1]), "r"(a[2]), "r"(a[3]), "r"(b0), "r"(b1));
}
__device__ __forceinline__ void cpa16(uint32_t dst, const void* src, uint32_t sz) {
    asm volatile("cp.async.ca.shared.global [%0], [%1], 16, %2;"
                 :: "r"(dst), "l"(src), "r"(sz));
}
__device__ __forceinline__ void cpa_commit() {
    asm volatile("cp.async.commit_group;" ::: "memory");
}
template<int N> __device__ __forceinline__ void cpa_wait() {
    asm volatile("cp.async.wait_group %0;" :: "n"(N) : "memory");
}

__device__ __forceinline__ void bsplit(float x, __nv_bfloat16& h, __nv_bfloat16& l) {
    h = __float2bfloat16(x);
    l = __float2bfloat16(x - __bfloat162float(h));
}
__device__ __forceinline__ void store_split4(__nv_bfloat16* oh, __nv_bfloat16* ol,
                                             size_t base, float4 v) {
    __nv_bfloat16 h0, h1, h2, h3, l0, l1, l2, l3;
    bsplit(v.x, h0, l0); bsplit(v.y, h1, l1); bsplit(v.z, h2, l2); bsplit(v.w, h3, l3);
    __nv_bfloat162 a = {h0, h1}, b = {h2, h3}, c = {l0, l1}, d = {l2, l3};
    *(__nv_bfloat162*)(oh + base) = a;
    *(__nv_bfloat162*)(oh + base + 2) = b;
    *(__nv_bfloat162*)(ol + base) = c;
    *(__nv_bfloat162*)(ol + base + 2) = d;
}
__device__ __forceinline__ void store_split2(__nv_bfloat16* oh, __nv_bfloat16* ol,
                                             size_t base, float v0, float v1) {
    __nv_bfloat16 h0, h1, l0, l1;
    bsplit(v0, h0, l0); bsplit(v1, h1, l1);
    __nv_bfloat162 a = {h0, h1}, c = {l0, l1};
    *(__nv_bfloat162*)(oh + base) = a;
    *(__nv_bfloat162*)(ol + base) = c;
}

// ---------------- degree + CSR build ----------------
__global__ void k_zero_deg() {
    int i = blockIdx.x * blockDim.x + threadIdx.x;
    if (i < NND) g_deg[i] = 0;
}
__global__ void k_deg(const int* __restrict__ v) {
    int i = blockIdx.x * blockDim.x + threadIdx.x;
    if (i < NE) atomicAdd(&g_deg[v[i]], 1);
}
// level-1: per-block (512 nodes) exclusive scan via warp shuffles
__global__ void k_scan1() {
    __shared__ int wsum[16];
    int t = threadIdx.x;
    int i = blockIdx.x * 512 + t;
    int x = (i < NND) ? g_deg[i] : 0;
    int incl = x;
#pragma unroll
    for (int o = 1; o < 32; o <<= 1) {
        int y = __shfl_up_sync(0xffffffffu, incl, o);
        if ((t & 31) >= o) incl += y;
    }
    if ((t & 31) == 31) wsum[t >> 5] = incl;
    __syncthreads();
    if (t < 16) {
        int s = wsum[t];
#pragma unroll
        for (int o = 1; o < 16; o <<= 1) {
            int y = __shfl_up_sync(0xffffu, s, o);
            if (t >= o) s += y;
        }
        wsum[t] = s;
    }
    __syncthreads();
    int woff = (t >> 5) ? wsum[(t >> 5) - 1] : 0;
    if (i < NND) g_start[i] = woff + incl - x;
    if (t == 511) g_bsum[blockIdx.x] = woff + incl;
}
// level-2: scan the 98 block sums (1 block, 128 threads)
__global__ void k_scan2() {
    __shared__ int sh[128];
    int t = threadIdx.x;
    int x = (t < NB_SCAN) ? g_bsum[t] : 0;
    sh[t] = x;
    __syncthreads();
#pragma unroll
    for (int o = 1; o < 128; o <<= 1) {
        int y = (t >= o) ? sh[t - o] : 0;
        __syncthreads();
        sh[t] += y;
        __syncthreads();
    }
    if (t < NB_SCAN) g_boff[t] = sh[t] - x;
    if (t == 0) g_start[NND] = NE;
}
// level-3: add block offsets
__global__ void k_scan3() {
    int i = blockIdx.x * blockDim.x + threadIdx.x;
    if (i >= NND) return;
    int s = g_start[i] + g_boff[i >> 9];
    g_start[i] = s;
    g_fill[i] = s;
}
__global__ void k_bin(const int* __restrict__ u, const int* __restrict__ v) {
    int e = blockIdx.x * blockDim.x + threadIdx.x;
    if (e >= NE) return;
    int pos = atomicAdd(&g_fill[v[e]], 1);
    g_csr[pos] = make_int2(e, u[e]);
}

// ---------------- prep: nfeats -> X1[:,0:64] split; weights -> transposed split ----------------
__global__ void k_prep(const float* __restrict__ nf, const float* __restrict__ W1a,
                       const float* __restrict__ W1e, const float* __restrict__ W2a,
                       const float* __restrict__ W2e) {
    int id = blockIdx.x * blockDim.x + threadIdx.x;
    if (id < NND * 64) {
        int r = id >> 6, c = id & 63;
        __nv_bfloat16 h, l;
        bsplit(nf[id], h, l);
        g_x1h[(size_t)r * 192 + c] = h;
        g_x1l[(size_t)r * 192 + c] = l;
        return;
    }
    id -= NND * 64;
    const float* W; int K, o;
    if      (id < 24576)  { W = W1a;           K = 192; o = O_W1A; }
    else if (id < 40960)  { W = W1e;           K = 128; o = O_W1ET; id -= 24576; }
    else if (id < 57344)  { W = W1e + 16384;   K = 128; o = O_W1EB; id -= 40960; }
    else if (id < 106496) { W = W2a;           K = 384; o = O_W2A;  id -= 57344; }
    else if (id < 122880) { W = W2e;           K = 128; o = O_W2ET; id -= 106496; }
    else if (id < 139264) { W = W2e + 16384;   K = 128; o = O_W2EB; id -= 122880; }
    else return;
    int k = id >> 7, n = id & 127;
    __nv_bfloat16 h, l;
    bsplit(W[(size_t)k * 128 + n], h, l);
    g_wth[o + n * K + k] = h;
    g_wtl[o + n * K + k] = l;
}

// ---------------- layer-1 aggregation -> bf16 split into X1[:,64:192] ----------------
__global__ void k_agg1(const float* __restrict__ nf, const float* __restrict__ ef) {
    int w = (blockIdx.x * blockDim.x + threadIdx.x) >> 5;
    if (w >= NND) return;
    int q = threadIdx.x & 31;
    int s = g_start[w], e_end = g_start[w + 1];
    float4 acc = make_float4(0.f, 0.f, 0.f, 0.f);
    for (int i = s; i < e_end; i++) {
        int2 eu = g_csr[i];
        const float* src;
        if (q < 16) src = nf + (size_t)eu.y * 64 + q * 4;
        else        src = ef + (size_t)eu.x * 64 + (q - 16) * 4;
        float4 val = *(const float4*)src;
        acc.x += val.x; acc.y += val.y; acc.z += val.z; acc.w += val.w;
    }
    float inv = 1.0f / fmaxf((float)(e_end - s), 1.0f);
    acc.x *= inv; acc.y *= inv; acc.z *= inv; acc.w *= inv;
    store_split4(g_x1h, g_x1l, (size_t)w * 192 + 64 + q * 4, acc);
}

// ---------------- layer-2 aggregation (he1 fused) -> bf16 split into X2[:,128:384] ----------------
__global__ void k_agg2(const float* __restrict__ bias) {
    int w = (blockIdx.x * blockDim.x + threadIdx.x) >> 5;
    if (w >= NND) return;
    int q = threadIdx.x & 31;
    int f = q * 4;
    int s = g_start[w], e_end = g_start[w + 1];
    float4 b  = *(const float4*)(g_B + (size_t)w * 128 + f);
    float4 bs = *(const float4*)(bias + f);
    b.x += bs.x; b.y += bs.y; b.z += bs.z; b.w += bs.w;
    float4 ah = make_float4(0.f, 0.f, 0.f, 0.f);
    float4 ae = make_float4(0.f, 0.f, 0.f, 0.f);
    for (int i = s; i < e_end; i++) {
        int uu = g_csr[i].y;
        float4 h = *(const float4*)(g_hn1 + (size_t)uu * 128 + f);
        float4 a = *(const float4*)(g_A   + (size_t)uu * 128 + f);
        ah.x += h.x; ah.y += h.y; ah.z += h.z; ah.w += h.w;
        ae.x += fmaxf(a.x + b.x, 0.f);
        ae.y += fmaxf(a.y + b.y, 0.f);
        ae.z += fmaxf(a.z + b.z, 0.f);
        ae.w += fmaxf(a.w + b.w, 0.f);
    }
    float inv = 1.0f / fmaxf((float)(e_end - s), 1.0f);
    ah.x *= inv; ah.y *= inv; ah.z *= inv; ah.w *= inv;
    ae.x *= inv; ae.y *= inv; ae.z *= inv; ae.w *= inv;
    store_split4(g_x2h, g_x2l, (size_t)w * 384 + 128 + f, ah);
    store_split4(g_x2h, g_x2l, (size_t)w * 384 + 256 + f, ae);
}

// ---------------- final edges: he2 = relu(A2[u]+B2[v]+b) -> d_out ----------------
__global__ void k_edge2(const int* __restrict__ u, const int* __restrict__ v,
                        const float* __restrict__ bias, float* __restrict__ out_he) {
    int tid = blockIdx.x * blockDim.x + threadIdx.x;
    int e = tid >> 5;
    if (e >= NE) return;
    int q = tid & 31;
    int f = q * 4;
    int uu = u[e], vv = v[e];
    float4 a  = *(const float4*)(g_A + (size_t)uu * 128 + f);
    float4 b  = *(const float4*)(g_B + (size_t)vv * 128 + f);
    float4 bs = *(const float4*)(bias + f);
    float4 r;
    r.x = fmaxf(a.x + b.x + bs.x, 0.0f);
    r.y = fmaxf(a.y + b.y + bs.y, 0.0f);
    r.z = fmaxf(a.z + b.z + bs.z, 0.0f);
    r.w = fmaxf(a.w + b.w + bs.w, 0.0f);
    *(float4*)(out_he + (size_t)e * 128 + f) = r;
}

// ---------------- warp-MMA GEMM (cp.async double-buffered) ----------------
// out[M,128] = relu?(X @ Wt^T + bias); X split [R,K_DIM] stride ldx; Wt split [128,K_DIM] K-major.
// mma.sync m16n8k16 bf16, 3-term split. Block 256 thr = 8 warps (4M x 2N); tile 128x128.
// Smem: 2 stages x 64KB (AH|AL|BH|BL 16KB each).
template<int K_DIM, bool RELU, bool BF16OUT>
__global__ void __launch_bounds__(256, 1)
k_mma(const __nv_bfloat16* __restrict__ Xh, const __nv_bfloat16* __restrict__ Xl, int ldx,
      const __nv_bfloat16* __restrict__ Wh, const __nv_bfloat16* __restrict__ Wl,
      const float* __restrict__ bias, float* __restrict__ out32,
      __nv_bfloat16* __restrict__ oh, __nv_bfloat16* __restrict__ ol, int ldo, int R)
{
    extern __shared__ char sm[];
    const int AH = 0, AL = 16384, BH = 32768, BL = 49152, STG = 65536;
    uint32_t sb = smem_u32(sm);
    int t = threadIdx.x, wid = t >> 5, lane = t & 31;
    int row0 = blockIdx.x * 128;
    int m_base = (wid & 3) * 32;
    int n_base = (wid >> 2) * 64;

    float acc[2][8][4];
#pragma unroll
    for (int i = 0; i < 2; i++)
#pragma unroll
        for (int j = 0; j < 8; j++)
#pragma unroll
            for (int q = 0; q < 4; q++) acc[i][j][q] = 0.0f;

    const int g = lane >> 3, r8 = lane & 7;
    const int a_ro = ((g & 1) << 3) + r8;
    const int a_ko = (g >> 1) << 3;
    const int b_ro = ((g >> 1) << 3) + r8;
    const int b_ko = (g & 1) << 3;

    const int srow = t >> 3, sj = t & 7;          // staging: 32 rows per pass, 8 cols
    const bool svalid = true;                      // per-i validity computed below
    const int NCH = K_DIM / 64;

    // stage loader: chunk kc into stage s
    auto stage_load = [&](int kc, int s) {
        int kc0 = kc * 64;
        uint32_t base = sb + s * STG;
#pragma unroll
        for (int i = 0; i < 4; i++) {
            int row = srow + i * 32;
            uint32_t so = SWZ(row * 128 + sj * 16);
            bool ok = (row0 + row < R);
            size_t go = (size_t)(ok ? row0 + row : 0) * ldx + kc0 + sj * 8;
            uint32_t sz = ok ? 16u : 0u;
            cpa16(base + AH + so, Xh + go, sz);
            cpa16(base + AL + so, Xl + go, sz);
            size_t wo = (size_t)row * K_DIM + kc0 + sj * 8;
            cpa16(base + BH + so, Wh + wo, 16u);
            cpa16(base + BL + so, Wl + wo, 16u);
        }
        cpa_commit();
    };

    stage_load(0, 0);
    for (int kc = 0; kc < NCH; kc++) {
        if (kc + 1 < NCH) {
            stage_load(kc + 1, (kc + 1) & 1);
            cpa_wait<1>();
        } else {
            cpa_wait<0>();
        }
        __syncthreads();
        uint32_t base = sb + (kc & 1) * STG;
        (void)svalid;
#pragma unroll
        for (int ks = 0; ks < 4; ks++) {
            int k0 = ks * 16;
            uint32_t ah[2][4], al[2][4];
#pragma unroll
            for (int mt = 0; mt < 2; mt++) {
                uint32_t off = SWZ((m_base + mt * 16 + a_ro) * 128 + (k0 + a_ko) * 2);
                ldm4(ah[mt], base + AH + off);
                ldm4(al[mt], base + AL + off);
            }
#pragma unroll
            for (int np = 0; np < 4; np++) {
                uint32_t boff = SWZ((n_base + np * 16 + b_ro) * 128 + (k0 + b_ko) * 2);
                uint32_t bh[4], bl[4];
                ldm4(bh, base + BH + boff);
                ldm4(bl, base + BL + boff);
#pragma unroll
                for (int mt = 0; mt < 2; mt++) {
                    mma16816(acc[mt][np * 2], ah[mt], bh[0], bh[1]);
                    mma16816(acc[mt][np * 2], ah[mt], bl[0], bl[1]);
                    mma16816(acc[mt][np * 2], al[mt], bh[0], bh[1]);
                    mma16816(acc[mt][np * 2 + 1], ah[mt], bh[2], bh[3]);
                    mma16816(acc[mt][np * 2 + 1], ah[mt], bl[2], bl[3]);
                    mma16816(acc[mt][np * 2 + 1], al[mt], bh[2], bh[3]);
                }
            }
        }
        __syncthreads();
    }

    // ---- epilogue ----
    const int rl = lane >> 2, cl = (lane & 3) * 2;
#pragma unroll
    for (int mt = 0; mt < 2; mt++) {
#pragma unroll
        for (int h = 0; h < 2; h++) {
            int row = row0 + m_base + mt * 16 + h * 8 + rl;
            if (row >= R) continue;
#pragma unroll
            for (int nt = 0; nt < 8; nt++) {
                int col = n_base + nt * 8 + cl;
                float v0 = acc[mt][nt][h * 2 + 0];
                float v1 = acc[mt][nt][h * 2 + 1];
                if (RELU) {
                    float2 bs = *(const float2*)(bias + col);
                    v0 = fmaxf(v0 + bs.x, 0.f);
                    v1 = fmaxf(v1 + bs.y, 0.f);
                }
                float2 vv = {v0, v1};
                *(float2*)(out32 + (size_t)row * 128 + col) = vv;
                if (BF16OUT) store_split2(oh, ol, (size_t)row * ldo + col, v0, v1);
            }
        }
    }
}

// ---------------- launcher ----------------
extern "C" void kernel_launch(void* const* d_in, const int* in_sizes, int n_in,
                              void* d_out, int out_size) {
    const float* nfeats = (const float*)d_in[0];
    const float* efeats = (const float*)d_in[1];
    const float* W1a_w  = (const float*)d_in[2];
    const float* W1a_b  = (const float*)d_in[3];
    const float* W1e_w  = (const float*)d_in[4];
    const float* W1e_b  = (const float*)d_in[5];
    const float* W2a_w  = (const float*)d_in[6];
    const float* W2a_b  = (const float*)d_in[7];
    const float* W2e_w  = (const float*)d_in[8];
    const float* W2e_b  = (const float*)d_in[9];
    const int*   u      = (const int*)d_in[10];
    const int*   v      = (const int*)d_in[11];

    float* out_hn = (float*)d_out;                        // [NND, 128]
    float* out_he = out_hn + (size_t)NND * 128;           // [NE, 128]

    void *p;
    cudaGetSymbolAddress(&p, g_hn1); float* hn1 = (float*)p;
    cudaGetSymbolAddress(&p, g_A);   float* A   = (float*)p;
    cudaGetSymbolAddress(&p, g_B);   float* B   = (float*)p;
    cudaGetSymbolAddress(&p, g_x1h); __nv_bfloat16* x1h = (__nv_bfloat16*)p;
    cudaGetSymbolAddress(&p, g_x1l); __nv_bfloat16* x1l = (__nv_bfloat16*)p;
    cudaGetSymbolAddress(&p, g_x2h); __nv_bfloat16* x2h = (__nv_bfloat16*)p;
    cudaGetSymbolAddress(&p, g_x2l); __nv_bfloat16* x2l = (__nv_bfloat16*)p;
    cudaGetSymbolAddress(&p, g_xoh); __nv_bfloat16* xoh = (__nv_bfloat16*)p;
    cudaGetSymbolAddress(&p, g_xol); __nv_bfloat16* xol = (__nv_bfloat16*)p;
    cudaGetSymbolAddress(&p, g_wth); __nv_bfloat16* wth = (__nv_bfloat16*)p;
    cudaGetSymbolAddress(&p, g_wtl); __nv_bfloat16* wtl = (__nv_bfloat16*)p;

    const int SMG = 131072;   // 2 x 64KB stages
    cudaFuncSetAttribute(k_mma<192, true, true>,   cudaFuncAttributeMaxDynamicSharedMemorySize, SMG);
    cudaFuncSetAttribute(k_mma<384, true, true>,   cudaFuncAttributeMaxDynamicSharedMemorySize, SMG);
    cudaFuncSetAttribute(k_mma<128, false, false>, cudaFuncAttributeMaxDynamicSharedMemorySize, SMG);

    const int EDGE_BLOCKS = (NE * 32 + 255) / 256;
    const int NODE_WARPS  = (NND * 32 + 255) / 256;
    const int GB = (NND + 127) / 128;                     // 391
    const int PREP = (NND * 64 + 139264 + 255) / 256;

    // ---- CSR build + prep ----
    k_zero_deg<<<(NND + 255) / 256, 256>>>();
    k_deg<<<(NE + 255) / 256, 256>>>(v);
    k_scan1<<<NB_SCAN, 512>>>();
    k_scan2<<<1, 128>>>();
    k_scan3<<<(NND + 255) / 256, 256>>>();
    k_bin<<<(NE + 255) / 256, 256>>>(u, v);
    k_prep<<<PREP, 256>>>(nfeats, W1a_w, W1e_w, W2a_w, W2e_w);

    // ---- layer 1 ----
    k_agg1<<<NODE_WARPS, 256>>>(nfeats, efeats);
    k_mma<192, true, true><<<GB, 256, SMG>>>(x1h, x1l, 192, wth + O_W1A, wtl + O_W1A,
                                             W1a_b, hn1, x2h, x2l, 384, NND);
    k_mma<128, false, false><<<GB, 256, SMG>>>(x2h, x2l, 384, wth + O_W1ET, wtl + O_W1ET,
                                               nullptr, A, nullptr, nullptr, 0, NND);
    k_mma<128, false, false><<<GB, 256, SMG>>>(x2h, x2l, 384, wth + O_W1EB, wtl + O_W1EB,
                                               nullptr, B, nullptr, nullptr, 0, NND);

    // ---- layer 2 ----
    k_agg2<<<NODE_WARPS, 256>>>(W1e_b);
    k_mma<384, true, true><<<GB, 256, SMG>>>(x2h, x2l, 384, wth + O_W2A, wtl + O_W2A,
                                             W2a_b, out_hn, xoh, xol, 128, NND);
    k_mma<128, false, false><<<GB, 256, SMG>>>(xoh, xol, 128, wth + O_W2ET, wtl + O_W2ET,
                                               nullptr, A, nullptr, nullptr, 0, NND);
    k_mma<128, false, false><<<GB, 256, SMG>>>(xoh, xol, 128, wth + O_W2EB, wtl + O_W2EB,
                                               nullptr, B, nullptr, nullptr, 0, NND);
    k_edge2<<<EDGE_BLOCKS, 256>>>(u, v, W2e_b, out_he);
}